// round 15
// baseline (speedup 1.0000x reference)
#include <cuda_runtime.h>
#include <cuda_fp16.h>
#include <cstdint>

// ---------------------------------------------------------------------------
// HeteroSTHN head via mma.sync HMMA fp16 (fp32 accum).
// BM=64, 256 threads, 8 warps: warp (mw, nw) owns m-rows [mw*16,+16) of all
// 3 matrices x n-half nw*56. Double-buffered cp.async B pipeline with
// byte-exact pre-staged images. 2 CTAs/SM.
// T-SPLIT: 2 CTAs per edge-block (t 0-3 / 4-7) -> 2048 uniform blocks kills
// the 4-wave quantization tail; partial maxes merged by a tiny second kernel.
//
//   enc_src = h_src @ src_W + src_b   (bias folded as K row 200, A=1.0)
//   enc_dst = h_dst @ dst_W + dst_b
//   pred[n,t] = relu(enc_src + enc_dst) @ out_W[t] + out_b[t]
//   out[n] = masked max over t (pos);  out[E+n] = masked max over t (neg)
// ---------------------------------------------------------------------------

#define TT    8
#define DDIM  200
#define HDIM  100
#define KPAD  208            // 13 ksteps of 16 (k=200 is the bias row)
#define BM    64
#define NTHR  256
#define EMAX  65536

// ---- smem layout (bytes) ----
#define OFF_RED  0                       // 4 mw * 8 qr * 4 floats = 512
#define OFF_A    512
#define A_ROWB   432                     // 208k*2B=416 +16 pad (conflict-free)
#define A_SZ     (192 * A_ROWB)          // 82944 (3 mats x 64 rows)
#define OFF_B    (OFF_A + A_SZ)          // 83456
#define B_ROWB   240                     // 112n*2B=224 +16 pad (conflict-free)
#define B_SET    (32 * B_ROWB)           // 7680 per wm set
#define B_BUF    (2 * B_SET)             // 15360 per pipeline buffer
#define SMEM_TOTAL (OFF_B + 2 * B_BUF)   // 114176  (x2 CTAs <= 232448)

#define NCHUNK  7                        // 6 x 32 + 1 x 16 k-rows per t
#define NT_H    4                        // t's per CTA (t-split)
#define NCT_H   (NT_H * NCHUNK)          // 28 pipeline steps per CTA
#define NI16    (B_BUF / 16)             // 960 16B groups per chunk image

// g_B: byte-exact smem images, [t][chunk] x 15360 B
__device__ __align__(16) unsigned char g_B[(size_t)TT * NCHUNK * B_BUF]; // 860 KB
// partial results: [pn][thalf][E]
__device__ float g_P[2 * 2 * EMAX];                                      // 1 MB

// ---------------- asm helpers ----------------
__device__ __forceinline__ uint32_t smem_u32(const void* p) {
    uint32_t a;
    asm("{ .reg .u64 t; cvta.to.shared.u64 t, %1; cvt.u32.u64 %0, t; }" : "=r"(a) : "l"(p));
    return a;
}

#define LDSM_X4(R0,R1,R2,R3,ADDR) \
    asm volatile("ldmatrix.sync.aligned.m8n8.x4.shared.b16 {%0,%1,%2,%3}, [%4];" \
        : "=r"(R0), "=r"(R1), "=r"(R2), "=r"(R3) : "r"(ADDR))

#define LDSM_X4T(R0,R1,R2,R3,ADDR) \
    asm volatile("ldmatrix.sync.aligned.m8n8.x4.trans.shared.b16 {%0,%1,%2,%3}, [%4];" \
        : "=r"(R0), "=r"(R1), "=r"(R2), "=r"(R3) : "r"(ADDR))

#define LDSM_X2T(R0,R1,ADDR) \
    asm volatile("ldmatrix.sync.aligned.m8n8.x2.trans.shared.b16 {%0,%1}, [%2];" \
        : "=r"(R0), "=r"(R1) : "r"(ADDR))

#define MMA4(C, A, B0, B1) \
    asm volatile("mma.sync.aligned.m16n8k16.row.col.f32.f16.f16.f32 " \
        "{%0,%1,%2,%3}, {%4,%5,%6,%7}, {%8,%9}, {%0,%1,%2,%3};" \
        : "+f"((C)[0]), "+f"((C)[1]), "+f"((C)[2]), "+f"((C)[3]) \
        : "r"((A)[0]), "r"((A)[1]), "r"((A)[2]), "r"((A)[3]), "r"(B0), "r"(B1))

// d = a*b + 0  (zero C operand -> no explicit accumulator clearing)
#define MMA4Z(C, A, B0, B1) \
    asm volatile("mma.sync.aligned.m16n8k16.row.col.f32.f16.f16.f32 " \
        "{%0,%1,%2,%3}, {%4,%5,%6,%7}, {%8,%9}, {%10,%10,%10,%10};" \
        : "=f"((C)[0]), "=f"((C)[1]), "=f"((C)[2]), "=f"((C)[3]) \
        : "r"((A)[0]), "r"((A)[1]), "r"((A)[2]), "r"((A)[3]), "r"(B0), "r"(B1), \
          "f"(0.0f))

#define CP_ASYNC16(SMEM, GPTR) \
    asm volatile("cp.async.cg.shared.global [%0], [%1], 16;" :: "r"(SMEM), "l"(GPTR))
#define CP_COMMIT()  asm volatile("cp.async.commit_group;" ::: "memory")
#define CP_WAIT0()   asm volatile("cp.async.wait_group 0;" ::: "memory")

// ---------------------------------------------------------------------------
// prep B: build the byte-exact smem image (unchanged from R14).
// ---------------------------------------------------------------------------
__global__ void prepB_kernel(const float* __restrict__ srcW, const float* __restrict__ srcb,
                             const float* __restrict__ dstW, const float* __restrict__ dstb) {
    const int gid = blockIdx.x * 256 + threadIdx.x;
    const int total = TT * NCHUNK * NI16;            // 53760 16B groups
    if (gid >= total) return;
    const int i16 = gid % NI16;
    const int tc  = gid / NI16;
    const int c   = tc % NCHUNK;
    const int t   = tc / NCHUNK;
    const int set = i16 / (NI16 / 2);
    const int rr  = i16 % (NI16 / 2);
    const int kr  = rr / 15;
    const int q   = rr % 15;
    const int k   = c * 32 + kr;

    const float* W  = set ? dstW : srcW;
    const float* bb = set ? dstb : srcb;

    __align__(16) uint16_t hb[8];
    #pragma unroll
    for (int j = 0; j < 8; ++j) {
        const int n = q * 8 + j;
        float v = 0.0f;
        if (q < 14 && n < HDIM && k <= DDIM) {
            if (k < DDIM)  v = W[((size_t)t * DDIM + k) * HDIM + n];
            else           v = bb[t * HDIM + n];     // k == DDIM: bias row
        }
        const __half x = __float2half(v);
        hb[j] = *reinterpret_cast<const uint16_t*>(&x);
    }
    *reinterpret_cast<uint4*>(g_B + (size_t)tc * B_BUF + set * B_SET
                              + kr * B_ROWB + q * 16) = *reinterpret_cast<uint4*>(hb);
}

// ---------------------------------------------------------------------------
// merge: out[pn*E + e] from the two t-half partials
// ---------------------------------------------------------------------------
__global__ void merge_kernel(float* __restrict__ out, int E) {
    const int i = blockIdx.x * 256 + threadIdx.x;
    if (i >= 2 * E) return;
    const int pn = i / E, e = i - pn * E;
    const float v = fmaxf(g_P[(pn * 2 + 0) * EMAX + e],
                          g_P[(pn * 2 + 1) * EMAX + e]);
    out[i] = (v < -5e29f) ? 0.0f : v;
}

// ---------------------------------------------------------------------------
// per-kstep MMA body (uniform). FIRST uses zero-C form.
// ---------------------------------------------------------------------------
template<bool FIRST>
__device__ __forceinline__ void kstep(float (&C)[3][7][4],
                                      uint32_t a_addr0, uint32_t brow,
                                      uint32_t b_lane4, uint32_t b_lane2)
{
    uint32_t Ah[3][4];
    #pragma unroll
    for (int m = 0; m < 3; ++m)
        LDSM_X4(Ah[m][0], Ah[m][1], Ah[m][2], Ah[m][3],
                a_addr0 + (uint32_t)(m * 64 * A_ROWB));
    #pragma unroll
    for (int g = 0; g < 3; ++g) {
        uint32_t b0[4], b1[4];
        LDSM_X4T(b0[0], b0[1], b0[2], b0[3], brow + b_lane4 + (uint32_t)g * 32);
        LDSM_X4T(b1[0], b1[1], b1[2], b1[3], brow + b_lane4 + (uint32_t)g * 32 + B_SET);
        if (FIRST) {
            MMA4Z(C[0][2*g],   Ah[0], b0[0], b0[1]);
            MMA4Z(C[0][2*g+1], Ah[0], b0[2], b0[3]);
            MMA4Z(C[1][2*g],   Ah[1], b1[0], b1[1]);
            MMA4Z(C[1][2*g+1], Ah[1], b1[2], b1[3]);
            MMA4Z(C[2][2*g],   Ah[2], b1[0], b1[1]);
            MMA4Z(C[2][2*g+1], Ah[2], b1[2], b1[3]);
        } else {
            MMA4(C[0][2*g],   Ah[0], b0[0], b0[1]);
            MMA4(C[0][2*g+1], Ah[0], b0[2], b0[3]);
            MMA4(C[1][2*g],   Ah[1], b1[0], b1[1]);
            MMA4(C[1][2*g+1], Ah[1], b1[2], b1[3]);
            MMA4(C[2][2*g],   Ah[2], b1[0], b1[1]);
            MMA4(C[2][2*g+1], Ah[2], b1[2], b1[3]);
        }
    }
    {   // last 8 cols of this warp's 56-col window
        uint32_t c0[2], c1[2];
        LDSM_X2T(c0[0], c0[1], brow + b_lane2);
        LDSM_X2T(c1[0], c1[1], brow + b_lane2 + B_SET);
        if (FIRST) {
            MMA4Z(C[0][6], Ah[0], c0[0], c0[1]);
            MMA4Z(C[1][6], Ah[1], c1[0], c1[1]);
            MMA4Z(C[2][6], Ah[2], c1[0], c1[1]);
        } else {
            MMA4(C[0][6], Ah[0], c0[0], c0[1]);
            MMA4(C[1][6], Ah[1], c1[0], c1[1]);
            MMA4(C[2][6], Ah[2], c1[0], c1[1]);
        }
    }
}

// ---------------------------------------------------------------------------
// main kernel: blockIdx.x = blk*2 + thalf
// ---------------------------------------------------------------------------
__global__ __launch_bounds__(NTHR, 2)
void sthn_hmma_kernel(const float* __restrict__ h,
                      const float* __restrict__ outW, const float* __restrict__ outb,
                      const int* __restrict__ poss, int E)
{
    extern __shared__ char smem[];
    const uint32_t sb = smem_u32(smem);
    const int tid = threadIdx.x;
    const int w = tid >> 5, l = tid & 31;
    const int mw = w >> 1, nw = w & 1;
    const int thalf = blockIdx.x & 1;
    const int blk   = blockIdx.x >> 1;
    const int ctg0  = thalf * NCT_H;          // global image index base

    // ---- B chunk issue: pure linear copy of the 15360B image ----
    auto issueB = [&](int ctg, int buf) {
        const unsigned char* src = g_B + (size_t)ctg * B_BUF + tid * 16;
        uint32_t dst = sb + OFF_B + (uint32_t)(buf * B_BUF) + tid * 16;
        #pragma unroll
        for (int i = 0; i < NI16 / NTHR; ++i) {          // 3 full rounds
            CP_ASYNC16(dst, src);
            src += NTHR * 16; dst += NTHR * 16;
        }
        if (tid < NI16 - (NI16 / NTHR) * NTHR)           // remainder 192
            CP_ASYNC16(dst, src);
        CP_COMMIT();
    };

    issueB(ctg0, 0);     // first chunk in flight

    // ---- stage A once: fp32 h -> fp16, 192 rows x 26 groups of 8 k ----
    for (int i = tid; i < 192 * 26; i += NTHR) {
        const int row = i / 26, q = i % 26;
        const int m = row >> 6, r = row & 63;
        __align__(16) uint16_t hb[8];
        if (q < 25) {
            const float* hr = h + ((size_t)m * E + (size_t)blk * BM + r) * DDIM + q * 8;
            const float4 f0 = *reinterpret_cast<const float4*>(hr);
            const float4 f1 = *reinterpret_cast<const float4*>(hr + 4);
            *reinterpret_cast<__half2*>(hb + 0) = __floats2half2_rn(f0.x, f0.y);
            *reinterpret_cast<__half2*>(hb + 2) = __floats2half2_rn(f0.z, f0.w);
            *reinterpret_cast<__half2*>(hb + 4) = __floats2half2_rn(f1.x, f1.y);
            *reinterpret_cast<__half2*>(hb + 6) = __floats2half2_rn(f1.z, f1.w);
        } else {                             // k 200 = bias 1.0, 201..207 = 0
            hb[0] = 0x3C00; hb[1] = 0; hb[2] = 0; hb[3] = 0;
            hb[4] = 0; hb[5] = 0; hb[6] = 0; hb[7] = 0;
        }
        *reinterpret_cast<uint4*>(smem + OFF_A + row * A_ROWB + q * 16) =
            *reinterpret_cast<uint4*>(hb);
    }

    const int lr = l & 15, lc = l >> 4;            // ldmatrix lane addressing
    const int qr = l >> 2, qc = l & 3;             // C-fragment row/col in quad
    const uint32_t a_lane = (uint32_t)(OFF_A + (mw * 16 + lr) * A_ROWB + lc * 16);
    const uint32_t b_lane4 = (uint32_t)(lr * B_ROWB + lc * 16 + nw * 112);
    const uint32_t b_lane2 = (uint32_t)(lr * B_ROWB + nw * 112 + 96);

    float bests[4] = {-1e30f, -1e30f, -1e30f, -1e30f};

    float C[3][7][4];                      // initialized by MMA4Z on first kstep
    float* sRED = reinterpret_cast<float*>(smem + OFF_RED);

    for (int ct = 0; ct < NCT_H; ++ct) {
        const int c = ct % NCHUNK;
        const int t = thalf * NT_H + ct / NCHUNK;
        const int buf = ct & 1;

        CP_WAIT0();
        __syncthreads();

        if (ct + 1 < NCT_H) issueB(ctg0 + ct + 1, buf ^ 1);

        const int nk = (c < 6) ? 2 : 1;
        const uint32_t bbase = sb + OFF_B + (uint32_t)(buf * B_BUF);
        for (int ks = 0; ks < nk; ++ks) {
            const uint32_t a_addr0 = sb + a_lane + (uint32_t)((c * 32 + ks * 16) * 2);
            const uint32_t brow = bbase + (uint32_t)(ks * 16) * B_ROWB;
            if (c == 0 && ks == 0) kstep<true >(C, a_addr0, brow, b_lane4, b_lane2);
            else                   kstep<false>(C, a_addr0, brow, b_lane4, b_lane2);
        }

        if (c == NCHUNK - 1) {
            // ---- epilogue for t (out_W via __ldg; cols >= HDIM contribute 0) ----
            float pl = 0.f, ph = 0.f, nl = 0.f, nh = 0.f;
            const float* owg = outW + t * HDIM;
            const int col0 = nw * 56 + 2 * qc;
            #pragma unroll
            for (int nf = 0; nf < 7; ++nf) {
                const int n0 = col0 + nf * 8;
                const float ow0 = (n0     < HDIM) ? __ldg(owg + n0)     : 0.0f;
                const float ow1 = (n0 + 1 < HDIM) ? __ldg(owg + n0 + 1) : 0.0f;
                pl += fmaxf(C[0][nf][0] + C[1][nf][0], 0.f) * ow0
                    + fmaxf(C[0][nf][1] + C[1][nf][1], 0.f) * ow1;
                ph += fmaxf(C[0][nf][2] + C[1][nf][2], 0.f) * ow0
                    + fmaxf(C[0][nf][3] + C[1][nf][3], 0.f) * ow1;
                nl += fmaxf(C[0][nf][0] + C[2][nf][0], 0.f) * ow0
                    + fmaxf(C[0][nf][1] + C[2][nf][1], 0.f) * ow1;
                nh += fmaxf(C[0][nf][2] + C[2][nf][2], 0.f) * ow0
                    + fmaxf(C[0][nf][3] + C[2][nf][3], 0.f) * ow1;
            }
            #pragma unroll
            for (int off = 1; off < 4; off <<= 1) {
                pl += __shfl_xor_sync(0xffffffffu, pl, off);
                ph += __shfl_xor_sync(0xffffffffu, ph, off);
                nl += __shfl_xor_sync(0xffffffffu, nl, off);
                nh += __shfl_xor_sync(0xffffffffu, nh, off);
            }

            if (nw == 0 && qc == 0) {
                float* dst = sRED + (mw * 8 + qr) * 4;
                dst[0] = pl; dst[1] = ph; dst[2] = nl; dst[3] = nh;
            }
            __syncthreads();
            if (nw == 1 && qc == 0) {
                const float* ptn = sRED + (mw * 8 + qr) * 4;
                const float tpl = pl + ptn[0];
                const float tph = ph + ptn[1];
                const float tnl = nl + ptn[2];
                const float tnh = nh + ptn[3];

                const float ob = __ldg(outb + t);
                const int e_lo = blk * BM + mw * 16 + qr;
                const int e_hi = e_lo + 8;
                if (__ldg(poss + (size_t)e_lo * TT + t))
                    bests[0] = fmaxf(bests[0], tpl + ob);
                if (__ldg(poss + (size_t)e_hi * TT + t))
                    bests[1] = fmaxf(bests[1], tph + ob);
                if (__ldg(poss + ((size_t)E + e_lo) * TT + t))
                    bests[2] = fmaxf(bests[2], tnl + ob);
                if (__ldg(poss + ((size_t)E + e_hi) * TT + t))
                    bests[3] = fmaxf(bests[3], tnh + ob);
            }
        }
    }

    if (nw == 1 && qc == 0) {
        const int e_lo = blk * BM + mw * 16 + qr;
        const int e_hi = e_lo + 8;
        g_P[(0 * 2 + thalf) * EMAX + e_lo] = bests[0];
        g_P[(0 * 2 + thalf) * EMAX + e_hi] = bests[1];
        g_P[(1 * 2 + thalf) * EMAX + e_lo] = bests[2];
        g_P[(1 * 2 + thalf) * EMAX + e_hi] = bests[3];
    }
}

// ---------------------------------------------------------------------------
extern "C" void kernel_launch(void* const* d_in, const int* in_sizes, int n_in,
                              void* d_out, int out_size)
{
    const float* h    = (const float*)d_in[0];
    const float* srcW = (const float*)d_in[1];
    const float* srcb = (const float*)d_in[2];
    const float* dstW = (const float*)d_in[3];
    const float* dstb = (const float*)d_in[4];
    const float* outW = (const float*)d_in[5];
    const float* outb = (const float*)d_in[6];
    const int*   poss = (const int*)d_in[7];
    float* out = (float*)d_out;

    const int E = in_sizes[0] / (DDIM * 3);

    {
        const int totalB = TT * NCHUNK * NI16;       // 53760
        prepB_kernel<<<(totalB + 255) / 256, 256>>>(srcW, srcb, dstW, dstb);
    }

    cudaFuncSetAttribute(sthn_hmma_kernel,
                         cudaFuncAttributeMaxDynamicSharedMemorySize, SMEM_TOTAL);
    sthn_hmma_kernel<<<2 * (E / BM), NTHR, SMEM_TOTAL>>>(h, outW, outb, poss, E);

    merge_kernel<<<(2 * E + 255) / 256, 256>>>(out, E);
}

// round 16
// speedup vs baseline: 1.1310x; 1.1310x over previous
#include <cuda_runtime.h>
#include <cuda_fp16.h>
#include <cstdint>

// ---------------------------------------------------------------------------
// HeteroSTHN head via mma.sync HMMA fp16 (fp32 accum).
// BM=64, 256 threads, 8 warps: warp (mw, nw) owns m-rows [mw*16,+16) of all
// 3 matrices x n-half nw*56. Double-buffered cp.async B pipeline with
// byte-exact pre-staged images. 2 CTAs/SM.
// HYBRID TAIL-SPLIT: first NFULL=3*296 blocks run all 8 t (3 exact waves,
// write out directly); the remaining NBLK-NFULL edge-blocks are split into
// 2 half-CTAs (t 0-3 / 4-7) forming a short final wave; partials merged by
// a tiny second kernel. Kills the 13.5% wave-quantization tail.
//
//   enc_src = h_src @ src_W + src_b   (bias folded as K row 200, A=1.0)
//   enc_dst = h_dst @ dst_W + dst_b
//   pred[n,t] = relu(enc_src + enc_dst) @ out_W[t] + out_b[t]
//   out[n] = masked max over t (pos);  out[E+n] = masked max over t (neg)
// ---------------------------------------------------------------------------

#define TT    8
#define DDIM  200
#define HDIM  100
#define KPAD  208            // 13 ksteps of 16 (k=200 is the bias row)
#define BM    64
#define NTHR  256
#define EMAX  65536
#define NCONC 296            // 148 SMs x 2 CTAs

// ---- smem layout (bytes) ----
#define OFF_RED  0                       // 4 mw * 8 qr * 4 floats = 512
#define OFF_A    512
#define A_ROWB   432                     // 208k*2B=416 +16 pad (conflict-free)
#define A_SZ     (192 * A_ROWB)          // 82944 (3 mats x 64 rows)
#define OFF_B    (OFF_A + A_SZ)          // 83456
#define B_ROWB   240                     // 112n*2B=224 +16 pad (conflict-free)
#define B_SET    (32 * B_ROWB)           // 7680 per wm set
#define B_BUF    (2 * B_SET)             // 15360 per pipeline buffer
#define SMEM_TOTAL (OFF_B + 2 * B_BUF)   // 114176  (x2 CTAs <= 232448)

#define NCHUNK  7                        // 6 x 32 + 1 x 16 k-rows per t
#define NCT     (TT * NCHUNK)            // 56 steps (full CTA)
#define NCT_H   (4 * NCHUNK)             // 28 steps (half CTA)
#define NI16    (B_BUF / 16)             // 960 16B groups per chunk image

// g_B: byte-exact smem images, [t][chunk] x 15360 B
__device__ __align__(16) unsigned char g_B[(size_t)TT * NCHUNK * B_BUF]; // 860 KB
// partial results for split tail blocks: [pn][thalf][E]
__device__ float g_P[2 * 2 * EMAX];                                      // 1 MB

// ---------------- asm helpers ----------------
__device__ __forceinline__ uint32_t smem_u32(const void* p) {
    uint32_t a;
    asm("{ .reg .u64 t; cvta.to.shared.u64 t, %1; cvt.u32.u64 %0, t; }" : "=r"(a) : "l"(p));
    return a;
}

#define LDSM_X4(R0,R1,R2,R3,ADDR) \
    asm volatile("ldmatrix.sync.aligned.m8n8.x4.shared.b16 {%0,%1,%2,%3}, [%4];" \
        : "=r"(R0), "=r"(R1), "=r"(R2), "=r"(R3) : "r"(ADDR))

#define LDSM_X4T(R0,R1,R2,R3,ADDR) \
    asm volatile("ldmatrix.sync.aligned.m8n8.x4.trans.shared.b16 {%0,%1,%2,%3}, [%4];" \
        : "=r"(R0), "=r"(R1), "=r"(R2), "=r"(R3) : "r"(ADDR))

#define LDSM_X2T(R0,R1,ADDR) \
    asm volatile("ldmatrix.sync.aligned.m8n8.x2.trans.shared.b16 {%0,%1}, [%2];" \
        : "=r"(R0), "=r"(R1) : "r"(ADDR))

#define MMA4(C, A, B0, B1) \
    asm volatile("mma.sync.aligned.m16n8k16.row.col.f32.f16.f16.f32 " \
        "{%0,%1,%2,%3}, {%4,%5,%6,%7}, {%8,%9}, {%0,%1,%2,%3};" \
        : "+f"((C)[0]), "+f"((C)[1]), "+f"((C)[2]), "+f"((C)[3]) \
        : "r"((A)[0]), "r"((A)[1]), "r"((A)[2]), "r"((A)[3]), "r"(B0), "r"(B1))

// d = a*b + 0  (zero C operand -> no explicit accumulator clearing)
#define MMA4Z(C, A, B0, B1) \
    asm volatile("mma.sync.aligned.m16n8k16.row.col.f32.f16.f16.f32 " \
        "{%0,%1,%2,%3}, {%4,%5,%6,%7}, {%8,%9}, {%10,%10,%10,%10};" \
        : "=f"((C)[0]), "=f"((C)[1]), "=f"((C)[2]), "=f"((C)[3]) \
        : "r"((A)[0]), "r"((A)[1]), "r"((A)[2]), "r"((A)[3]), "r"(B0), "r"(B1), \
          "f"(0.0f))

#define CP_ASYNC16(SMEM, GPTR) \
    asm volatile("cp.async.cg.shared.global [%0], [%1], 16;" :: "r"(SMEM), "l"(GPTR))
#define CP_COMMIT()  asm volatile("cp.async.commit_group;" ::: "memory")
#define CP_WAIT0()   asm volatile("cp.async.wait_group 0;" ::: "memory")

// ---------------------------------------------------------------------------
// prep B: build the byte-exact smem image (unchanged from R14).
// ---------------------------------------------------------------------------
__global__ void prepB_kernel(const float* __restrict__ srcW, const float* __restrict__ srcb,
                             const float* __restrict__ dstW, const float* __restrict__ dstb) {
    const int gid = blockIdx.x * 256 + threadIdx.x;
    const int total = TT * NCHUNK * NI16;            // 53760 16B groups
    if (gid >= total) return;
    const int i16 = gid % NI16;
    const int tc  = gid / NI16;
    const int c   = tc % NCHUNK;
    const int t   = tc / NCHUNK;
    const int set = i16 / (NI16 / 2);
    const int rr  = i16 % (NI16 / 2);
    const int kr  = rr / 15;
    const int q   = rr % 15;
    const int k   = c * 32 + kr;

    const float* W  = set ? dstW : srcW;
    const float* bb = set ? dstb : srcb;

    __align__(16) uint16_t hb[8];
    #pragma unroll
    for (int j = 0; j < 8; ++j) {
        const int n = q * 8 + j;
        float v = 0.0f;
        if (q < 14 && n < HDIM && k <= DDIM) {
            if (k < DDIM)  v = W[((size_t)t * DDIM + k) * HDIM + n];
            else           v = bb[t * HDIM + n];     // k == DDIM: bias row
        }
        const __half x = __float2half(v);
        hb[j] = *reinterpret_cast<const uint16_t*>(&x);
    }
    *reinterpret_cast<uint4*>(g_B + (size_t)tc * B_BUF + set * B_SET
                              + kr * B_ROWB + q * 16) = *reinterpret_cast<uint4*>(hb);
}

// ---------------------------------------------------------------------------
// merge: tail edge-blocks only, e in [E0, E)
// ---------------------------------------------------------------------------
__global__ void merge_kernel(float* __restrict__ out, int E, int E0) {
    const int span = E - E0;
    const int i = blockIdx.x * 256 + threadIdx.x;
    if (i >= 2 * span) return;
    const int pn = i / span, e = E0 + (i - pn * span);
    const float v = fmaxf(g_P[(pn * 2 + 0) * EMAX + e],
                          g_P[(pn * 2 + 1) * EMAX + e]);
    out[pn * E + e] = (v < -5e29f) ? 0.0f : v;
}

// ---------------------------------------------------------------------------
// per-kstep MMA body (uniform). FIRST uses zero-C form.
// ---------------------------------------------------------------------------
template<bool FIRST>
__device__ __forceinline__ void kstep(float (&C)[3][7][4],
                                      uint32_t a_addr0, uint32_t brow,
                                      uint32_t b_lane4, uint32_t b_lane2)
{
    uint32_t Ah[3][4];
    #pragma unroll
    for (int m = 0; m < 3; ++m)
        LDSM_X4(Ah[m][0], Ah[m][1], Ah[m][2], Ah[m][3],
                a_addr0 + (uint32_t)(m * 64 * A_ROWB));
    #pragma unroll
    for (int g = 0; g < 3; ++g) {
        uint32_t b0[4], b1[4];
        LDSM_X4T(b0[0], b0[1], b0[2], b0[3], brow + b_lane4 + (uint32_t)g * 32);
        LDSM_X4T(b1[0], b1[1], b1[2], b1[3], brow + b_lane4 + (uint32_t)g * 32 + B_SET);
        if (FIRST) {
            MMA4Z(C[0][2*g],   Ah[0], b0[0], b0[1]);
            MMA4Z(C[0][2*g+1], Ah[0], b0[2], b0[3]);
            MMA4Z(C[1][2*g],   Ah[1], b1[0], b1[1]);
            MMA4Z(C[1][2*g+1], Ah[1], b1[2], b1[3]);
            MMA4Z(C[2][2*g],   Ah[2], b1[0], b1[1]);
            MMA4Z(C[2][2*g+1], Ah[2], b1[2], b1[3]);
        } else {
            MMA4(C[0][2*g],   Ah[0], b0[0], b0[1]);
            MMA4(C[0][2*g+1], Ah[0], b0[2], b0[3]);
            MMA4(C[1][2*g],   Ah[1], b1[0], b1[1]);
            MMA4(C[1][2*g+1], Ah[1], b1[2], b1[3]);
            MMA4(C[2][2*g],   Ah[2], b1[1 - 1], b1[1]);
            MMA4(C[2][2*g+1], Ah[2], b1[2], b1[3]);
        }
    }
    {   // last 8 cols of this warp's 56-col window
        uint32_t c0[2], c1[2];
        LDSM_X2T(c0[0], c0[1], brow + b_lane2);
        LDSM_X2T(c1[0], c1[1], brow + b_lane2 + B_SET);
        if (FIRST) {
            MMA4Z(C[0][6], Ah[0], c0[0], c0[1]);
            MMA4Z(C[1][6], Ah[1], c1[0], c1[1]);
            MMA4Z(C[2][6], Ah[2], c1[0], c1[1]);
        } else {
            MMA4(C[0][6], Ah[0], c0[0], c0[1]);
            MMA4(C[1][6], Ah[1], c1[0], c1[1]);
            MMA4(C[2][6], Ah[2], c1[0], c1[1]);
        }
    }
}

// ---------------------------------------------------------------------------
// main kernel: id < NFULL -> full 8t block; else split half-block
// ---------------------------------------------------------------------------
__global__ __launch_bounds__(NTHR, 2)
void sthn_hmma_kernel(const float* __restrict__ h,
                      const float* __restrict__ outW, const float* __restrict__ outb,
                      const int* __restrict__ poss, float* __restrict__ out,
                      int E, int NFULL)
{
    extern __shared__ char smem[];
    const uint32_t sb = smem_u32(smem);
    const int tid = threadIdx.x;
    const int w = tid >> 5, l = tid & 31;
    const int mw = w >> 1, nw = w & 1;

    const int id = blockIdx.x;
    int blk, t0, nct, thalf, isSplit;
    if (id < NFULL) { blk = id; t0 = 0; nct = NCT; thalf = 0; isSplit = 0; }
    else {
        const int s = id - NFULL;
        blk = NFULL + (s >> 1); thalf = s & 1;
        t0 = thalf * 4; nct = NCT_H; isSplit = 1;
    }
    const int ctg0 = t0 * NCHUNK;

    // ---- B chunk issue: pure linear copy of the 15360B image ----
    auto issueB = [&](int ctg, int buf) {
        const unsigned char* src = g_B + (size_t)ctg * B_BUF + tid * 16;
        uint32_t dst = sb + OFF_B + (uint32_t)(buf * B_BUF) + tid * 16;
        #pragma unroll
        for (int i = 0; i < NI16 / NTHR; ++i) {          // 3 full rounds
            CP_ASYNC16(dst, src);
            src += NTHR * 16; dst += NTHR * 16;
        }
        if (tid < NI16 - (NI16 / NTHR) * NTHR)           // remainder 192
            CP_ASYNC16(dst, src);
        CP_COMMIT();
    };

    issueB(ctg0, 0);     // first chunk in flight

    // ---- stage A once: fp32 h -> fp16, 192 rows x 26 groups of 8 k ----
    for (int i = tid; i < 192 * 26; i += NTHR) {
        const int row = i / 26, q = i % 26;
        const int m = row >> 6, r = row & 63;
        __align__(16) uint16_t hb[8];
        if (q < 25) {
            const float* hr = h + ((size_t)m * E + (size_t)blk * BM + r) * DDIM + q * 8;
            const float4 f0 = *reinterpret_cast<const float4*>(hr);
            const float4 f1 = *reinterpret_cast<const float4*>(hr + 4);
            *reinterpret_cast<__half2*>(hb + 0) = __floats2half2_rn(f0.x, f0.y);
            *reinterpret_cast<__half2*>(hb + 2) = __floats2half2_rn(f0.z, f0.w);
            *reinterpret_cast<__half2*>(hb + 4) = __floats2half2_rn(f1.x, f1.y);
            *reinterpret_cast<__half2*>(hb + 6) = __floats2half2_rn(f1.z, f1.w);
        } else {                             // k 200 = bias 1.0, 201..207 = 0
            hb[0] = 0x3C00; hb[1] = 0; hb[2] = 0; hb[3] = 0;
            hb[4] = 0; hb[5] = 0; hb[6] = 0; hb[7] = 0;
        }
        *reinterpret_cast<uint4*>(smem + OFF_A + row * A_ROWB + q * 16) =
            *reinterpret_cast<uint4*>(hb);
    }

    const int lr = l & 15, lc = l >> 4;            // ldmatrix lane addressing
    const int qr = l >> 2, qc = l & 3;             // C-fragment row/col in quad
    const uint32_t a_lane = (uint32_t)(OFF_A + (mw * 16 + lr) * A_ROWB + lc * 16);
    const uint32_t b_lane4 = (uint32_t)(lr * B_ROWB + lc * 16 + nw * 112);
    const uint32_t b_lane2 = (uint32_t)(lr * B_ROWB + nw * 112 + 96);

    float bests[4] = {-1e30f, -1e30f, -1e30f, -1e30f};

    float C[3][7][4];                      // initialized by MMA4Z on first kstep
    float* sRED = reinterpret_cast<float*>(smem + OFF_RED);

    for (int ct = 0; ct < nct; ++ct) {
        const int c = ct % NCHUNK;
        const int t = t0 + ct / NCHUNK;
        const int buf = ct & 1;

        CP_WAIT0();
        __syncthreads();

        if (ct + 1 < nct) issueB(ctg0 + ct + 1, buf ^ 1);

        const int nk = (c < 6) ? 2 : 1;
        const uint32_t bbase = sb + OFF_B + (uint32_t)(buf * B_BUF);
        for (int ks = 0; ks < nk; ++ks) {
            const uint32_t a_addr0 = sb + a_lane + (uint32_t)((c * 32 + ks * 16) * 2);
            const uint32_t brow = bbase + (uint32_t)(ks * 16) * B_ROWB;
            if (c == 0 && ks == 0) kstep<true >(C, a_addr0, brow, b_lane4, b_lane2);
            else                   kstep<false>(C, a_addr0, brow, b_lane4, b_lane2);
        }

        if (c == NCHUNK - 1) {
            // ---- epilogue for t (out_W via __ldg; cols >= HDIM contribute 0) ----
            float pl = 0.f, ph = 0.f, nl = 0.f, nh = 0.f;
            const float* owg = outW + t * HDIM;
            const int col0 = nw * 56 + 2 * qc;
            #pragma unroll
            for (int nf = 0; nf < 7; ++nf) {
                const int n0 = col0 + nf * 8;
                const float ow0 = (n0     < HDIM) ? __ldg(owg + n0)     : 0.0f;
                const float ow1 = (n0 + 1 < HDIM) ? __ldg(owg + n0 + 1) : 0.0f;
                pl += fmaxf(C[0][nf][0] + C[1][nf][0], 0.f) * ow0
                    + fmaxf(C[0][nf][1] + C[1][nf][1], 0.f) * ow1;
                ph += fmaxf(C[0][nf][2] + C[1][nf][2], 0.f) * ow0
                    + fmaxf(C[0][nf][3] + C[1][nf][3], 0.f) * ow1;
                nl += fmaxf(C[0][nf][0] + C[2][nf][0], 0.f) * ow0
                    + fmaxf(C[0][nf][1] + C[2][nf][1], 0.f) * ow1;
                nh += fmaxf(C[0][nf][2] + C[2][nf][2], 0.f) * ow0
                    + fmaxf(C[0][nf][3] + C[2][nf][3], 0.f) * ow1;
            }
            #pragma unroll
            for (int off = 1; off < 4; off <<= 1) {
                pl += __shfl_xor_sync(0xffffffffu, pl, off);
                ph += __shfl_xor_sync(0xffffffffu, ph, off);
                nl += __shfl_xor_sync(0xffffffffu, nl, off);
                nh += __shfl_xor_sync(0xffffffffu, nh, off);
            }

            if (nw == 0 && qc == 0) {
                float* dst = sRED + (mw * 8 + qr) * 4;
                dst[0] = pl; dst[1] = ph; dst[2] = nl; dst[3] = nh;
            }
            __syncthreads();
            if (nw == 1 && qc == 0) {
                const float* ptn = sRED + (mw * 8 + qr) * 4;
                const float tpl = pl + ptn[0];
                const float tph = ph + ptn[1];
                const float tnl = nl + ptn[2];
                const float tnh = nh + ptn[3];

                const float ob = __ldg(outb + t);
                const int e_lo = blk * BM + mw * 16 + qr;
                const int e_hi = e_lo + 8;
                if (__ldg(poss + (size_t)e_lo * TT + t))
                    bests[0] = fmaxf(bests[0], tpl + ob);
                if (__ldg(poss + (size_t)e_hi * TT + t))
                    bests[1] = fmaxf(bests[1], tph + ob);
                if (__ldg(poss + ((size_t)E + e_lo) * TT + t))
                    bests[2] = fmaxf(bests[2], tnl + ob);
                if (__ldg(poss + ((size_t)E + e_hi) * TT + t))
                    bests[3] = fmaxf(bests[3], tnh + ob);
            }
        }
    }

    if (nw == 1 && qc == 0) {
        const int e_lo = blk * BM + mw * 16 + qr;
        const int e_hi = e_lo + 8;
        if (!isSplit) {
            out[e_lo]     = (bests[0] < -5e29f) ? 0.0f : bests[0];
            out[e_hi]     = (bests[1] < -5e29f) ? 0.0f : bests[1];
            out[E + e_lo] = (bests[2] < -5e29f) ? 0.0f : bests[2];
            out[E + e_hi] = (bests[3] < -5e29f) ? 0.0f : bests[3];
        } else {
            g_P[(0 * 2 + thalf) * EMAX + e_lo] = bests[0];
            g_P[(0 * 2 + thalf) * EMAX + e_hi] = bests[1];
            g_P[(1 * 2 + thalf) * EMAX + e_lo] = bests[2];
            g_P[(1 * 2 + thalf) * EMAX + e_hi] = bests[3];
        }
    }
}

// ---------------------------------------------------------------------------
extern "C" void kernel_launch(void* const* d_in, const int* in_sizes, int n_in,
                              void* d_out, int out_size)
{
    const float* h    = (const float*)d_in[0];
    const float* srcW = (const float*)d_in[1];
    const float* srcb = (const float*)d_in[2];
    const float* dstW = (const float*)d_in[3];
    const float* dstb = (const float*)d_in[4];
    const float* outW = (const float*)d_in[5];
    const float* outb = (const float*)d_in[6];
    const int*   poss = (const int*)d_in[7];
    float* out = (float*)d_out;

    const int E    = in_sizes[0] / (DDIM * 3);
    const int NBLK = E / BM;
    int NFULL = (NBLK / NCONC) * NCONC;          // whole waves of full blocks
    if (NFULL == NBLK) NFULL = NBLK - NCONC;     // keep at least one split wave? no:
    if (NBLK % NCONC == 0) NFULL = NBLK;         // exact fit -> no split needed
    const int NSPLIT = NBLK - NFULL;

    {
        const int totalB = TT * NCHUNK * NI16;       // 53760
        prepB_kernel<<<(totalB + 255) / 256, 256>>>(srcW, srcb, dstW, dstb);
    }

    cudaFuncSetAttribute(sthn_hmma_kernel,
                         cudaFuncAttributeMaxDynamicSharedMemorySize, SMEM_TOTAL);
    sthn_hmma_kernel<<<NFULL + 2 * NSPLIT, NTHR, SMEM_TOTAL>>>(
        h, outW, outb, poss, out, E, NFULL);

    if (NSPLIT > 0) {
        const int span = NSPLIT * BM;
        merge_kernel<<<(2 * span + 255) / 256, 256>>>(out, E, NFULL * BM);
    }
}